// round 6
// baseline (speedup 1.0000x reference)
#include <cuda_runtime.h>

// Repacked grid: [B=4][Hg=16][Wg=16][D=8][16ch(pad)] = 131072 floats
__device__ float g_repack[4 * 16 * 16 * 8 * 16];

__global__ void repack_kernel(const float* __restrict__ G) {
    int i = blockIdx.x * blockDim.x + threadIdx.x;  // 131072 threads
    int c = i & 15;
    int t = i >> 4;
    int z = t & 7;  t >>= 3;
    int x = t & 15; t >>= 4;
    int y = t & 15;
    int b = t >> 4;
    float v = 0.0f;
    if (c < 12) {
        v = G[((b * 12 + c) * 8 + z) * 256 + y * 16 + x];
    }
    g_repack[i] = v;
}

// Shared x-interp table: T[sy][xl][z][12]
//   entry = 12 floats (48B = 3 16B-units; 3*z mod 8 is a permutation ->
//   z-divergent LDS.128 within an 8-lane phase is conflict-free)
//   xl stride 96 floats, sy stride 6144 floats. Total 49152B.
#define ZS 12
#define XS 96
#define SYS 6144

__device__ __forceinline__ void fma4(float4& acc, float w, const float4 v) {
    acc.x = fmaf(w, v.x, acc.x);
    acc.y = fmaf(w, v.y, acc.y);
    acc.z = fmaf(w, v.z, acc.z);
    acc.w = fmaf(w, v.w, acc.w);
}

__global__ __launch_bounds__(256, 4) void slice_apply_kernel(
    const float* __restrict__ guide,
    const float* __restrict__ fr,
    float* __restrict__ out)
{
    extern __shared__ float T[];

    const int b   = blockIdx.z;
    const int tx  = blockIdx.x;        // x grid-cell (tile 64 px wide)
    const int by  = blockIdx.y;        // 32-row tile index
    const int r0  = by << 5;
    const int tid = threadIdx.x;

    // 32-row aligned tiles never cross an fy boundary (boundaries at y=32+64k)
    const int   fy0  = (by - 1) >> 1;
    const float fy0f = (float)fy0;
    const int   gy0  = max(fy0, 0);
    const int   gy1  = min(fy0 + 1, 15);

    // ---- build table: 1024 entries, 4 per thread; z = lane-fast (conflict-free) ----
    {
        const int z    = tid & 7;
        const int rest = tid >> 3;         // 0..31
        const int xlq  = rest & 15;        // 4-px group 0..15
        const int sy   = rest >> 4;
        const int half = xlq >> 3;         // 0: xl<32 (fx0=tx-1), 1: xl>=32

        const int gy  = sy ? gy1 : gy0;
        const int gxa = half ? tx : max(tx - 1, 0);
        const int gxb = half ? min(tx + 1, 15) : tx;

        const float4* s0p = (const float4*)&g_repack[(((b * 16 + gy) * 16 + gxa) * 8 + z) * 16];
        const float4* s1p = (const float4*)&g_repack[(((b * 16 + gy) * 16 + gxb) * 8 + z) * 16];
        const float4 s0a = s0p[0], s0b = s0p[1], s0c = s0p[2];
        const float4 s1a = s1p[0], s1b = s1p[1], s1c = s1p[2];
        const float4 da = make_float4(s1a.x - s0a.x, s1a.y - s0a.y, s1a.z - s0a.z, s1a.w - s0a.w);
        const float4 db = make_float4(s1b.x - s0b.x, s1b.y - s0b.y, s1b.z - s0b.z, s1b.w - s0b.w);
        const float4 dc = make_float4(s1c.x - s0c.x, s1c.y - s0c.y, s1c.z - s0c.z, s1c.w - s0c.w);

        const int   xlb = xlq << 2;
        // wx = (xl+0.5)/64 + (half ? -0.5 : 0.5)
        const float wxb = ((float)xlb + 0.5f) * (1.0f / 64.0f) + (half ? -0.5f : 0.5f);

        #pragma unroll
        for (int k = 0; k < 4; k++) {
            const float wx = wxb + (float)k * (1.0f / 64.0f);
            float4* dst = (float4*)&T[sy * SYS + (xlb + k) * XS + z * ZS];
            dst[0] = make_float4(fmaf(wx, da.x, s0a.x), fmaf(wx, da.y, s0a.y),
                                 fmaf(wx, da.z, s0a.z), fmaf(wx, da.w, s0a.w));
            dst[1] = make_float4(fmaf(wx, db.x, s0b.x), fmaf(wx, db.y, s0b.y),
                                 fmaf(wx, db.z, s0b.z), fmaf(wx, db.w, s0b.w));
            dst[2] = make_float4(fmaf(wx, dc.x, s0c.x), fmaf(wx, dc.y, s0c.y),
                                 fmaf(wx, dc.z, s0c.z), fmaf(wx, dc.w, s0c.w));
        }
    }
    __syncthreads();

    // ---- main: thread = (8-px chunk, row). 8-lane phases share the chunk ->
    //      table LDS diverges only in z -> conflict-free / broadcast. ----
    const int lane   = tid & 31;
    const int warp   = tid >> 5;
    const int sub    = lane >> 3;          // 0..3
    const int rphase = lane & 7;           // 0..7
    const int chunk  = ((warp & 1) << 2) + sub;     // 0..7  (8 px each)
    const int row    = ((warp >> 1) << 3) + rphase; // 0..31

    const int x0 = chunk << 3;             // local x base 0..56
    const int y  = r0 + row;

    const float wy  = ((float)y + 0.5f) * (1.0f / 64.0f) - 0.5f - fy0f;
    const float wy0 = 1.0f - wy;

    const size_t gBase  = (size_t)b * 1048576u + ((size_t)y << 10) + (size_t)((tx << 6) + x0);
    const size_t frBase = (size_t)b * 3145728u + ((size_t)y << 10) + (size_t)((tx << 6) + x0);

    #pragma unroll
    for (int q = 0; q < 2; q++) {          // two 4-px quads
        const int qo = q << 2;
        const float4 g4  = *(const float4*)&guide[gBase + qo];
        const float4 fc0 = *(const float4*)&fr[frBase + qo];
        const float4 fc1 = *(const float4*)&fr[frBase + qo + 1048576u];
        const float4 fc2 = *(const float4*)&fr[frBase + qo + 2097152u];

        const float ga[4]  = {g4.x, g4.y, g4.z, g4.w};
        const float f0a[4] = {fc0.x, fc0.y, fc0.z, fc0.w};
        const float f1a[4] = {fc1.x, fc1.y, fc1.z, fc1.w};
        const float f2a[4] = {fc2.x, fc2.y, fc2.z, fc2.w};

        float o0[4], o1[4], o2[4];

        #pragma unroll
        for (int p = 0; p < 4; p++) {
            const float gz   = ga[p] * 8.0f - 0.5f;
            const float fz0f = floorf(gz);
            const float wz   = gz - fz0f;
            const int   fz0  = (int)fz0f;
            const int   z0   = max(fz0, 0);
            const int   z1   = min(fz0 + 1, 7);

            const float w00 = wy0 * (1.0f - wz);
            const float w01 = wy0 * wz;
            const float w10 = wy  * (1.0f - wz);
            const float w11 = wy  * wz;

            const int xb = (x0 + qo + p) * XS;
            const float4* t00 = (const float4*)&T[xb + z0 * ZS];
            const float4* t01 = (const float4*)&T[xb + z1 * ZS];
            const float4* t10 = (const float4*)&T[SYS + xb + z0 * ZS];
            const float4* t11 = (const float4*)&T[SYS + xb + z1 * ZS];

            float4 A  = make_float4(0.f, 0.f, 0.f, 0.f);
            float4 Bv = A, Cv = A;

            fma4(A, w00, t00[0]); fma4(Bv, w00, t00[1]); fma4(Cv, w00, t00[2]);
            fma4(A, w01, t01[0]); fma4(Bv, w01, t01[1]); fma4(Cv, w01, t01[2]);
            fma4(A, w10, t10[0]); fma4(Bv, w10, t10[1]); fma4(Cv, w10, t10[2]);
            fma4(A, w11, t11[0]); fma4(Bv, w11, t11[1]); fma4(Cv, w11, t11[2]);

            const float f0p = f0a[p], f1p = f1a[p], f2p = f2a[p];
            o0[p] = fmaf(A.x,  f0p, fmaf(A.y,  f1p, fmaf(A.z,  f2p, A.w)));
            o1[p] = fmaf(Bv.x, f0p, fmaf(Bv.y, f1p, fmaf(Bv.z, f2p, Bv.w)));
            o2[p] = fmaf(Cv.x, f0p, fmaf(Cv.y, f1p, fmaf(Cv.z, f2p, Cv.w)));
        }

        *(float4*)&out[frBase + qo]            = make_float4(o0[0], o0[1], o0[2], o0[3]);
        *(float4*)&out[frBase + qo + 1048576u] = make_float4(o1[0], o1[1], o1[2], o1[3]);
        *(float4*)&out[frBase + qo + 2097152u] = make_float4(o2[0], o2[1], o2[2], o2[3]);
    }
}

extern "C" void kernel_launch(void* const* d_in, const int* in_sizes, int n_in,
                              void* d_out, int out_size) {
    const float* G     = nullptr;
    const float* guide = nullptr;
    const float* fr    = nullptr;
    for (int i = 0; i < n_in; i++) {
        if (in_sizes[i] == 98304)          G     = (const float*)d_in[i];
        else if (in_sizes[i] == 4194304)   guide = (const float*)d_in[i];
        else if (in_sizes[i] == 12582912)  fr    = (const float*)d_in[i];
    }
    if (!G)     G     = (const float*)d_in[0];
    if (!guide) guide = (const float*)d_in[1];
    if (!fr)    fr    = (const float*)d_in[2];

    float* out = (float*)d_out;

    cudaFuncSetAttribute(slice_apply_kernel,
                         cudaFuncAttributeMaxDynamicSharedMemorySize, 49152);

    repack_kernel<<<512, 256>>>(G);

    dim3 grid(16, 32, 4);   // x-tiles(64px), y-tiles(32rows), batch
    slice_apply_kernel<<<grid, 256, 49152>>>(guide, fr, out);
}

// round 7
// speedup vs baseline: 1.0050x; 1.0050x over previous
#include <cuda_runtime.h>

// Repacked grid: [B=4][Hg=16][Wg=16][D=8][16ch(pad)] = 131072 floats
__device__ float g_repack[4 * 16 * 16 * 8 * 16];

__global__ void repack_kernel(const float* __restrict__ G) {
    int i = blockIdx.x * blockDim.x + threadIdx.x;  // 131072 threads
    int c = i & 15;
    int t = i >> 4;
    int z = t & 7;  t >>= 3;
    int x = t & 15; t >>= 4;
    int y = t & 15;
    int b = t >> 4;
    float v = 0.0f;
    if (c < 12) {
        v = G[((b * 12 + c) * 8 + z) * 256 + y * 16 + x];
    }
    g_repack[i] = v;
}

// Shared x-interp table: T[sy][xl][z][12]
//   entry = 12 floats (48B = 3 16B-units; 3*z mod 8 is a permutation ->
//   z-divergent LDS.128 within an 8-lane phase is conflict-free)
//   xl stride 96 floats, sy stride 6144 floats. Total 49152B.
#define ZS 12
#define XS 96
#define SYS 6144

__device__ __forceinline__ void fma4(float4& acc, float w, const float4 v) {
    acc.x = fmaf(w, v.x, acc.x);
    acc.y = fmaf(w, v.y, acc.y);
    acc.z = fmaf(w, v.z, acc.z);
    acc.w = fmaf(w, v.w, acc.w);
}

__global__ __launch_bounds__(256, 4) void slice_apply_kernel(
    const float* __restrict__ guide,
    const float* __restrict__ fr,
    float* __restrict__ out)
{
    extern __shared__ float T[];

    const int b   = blockIdx.z;
    const int tx  = blockIdx.x;        // x grid-cell (tile 64 px wide)
    const int by  = blockIdx.y;        // 32-row tile index
    const int r0  = by << 5;
    const int tid = threadIdx.x;

    // 32-row aligned tiles never cross an fy boundary (boundaries at y=32+64k)
    const int   fy0  = (by - 1) >> 1;
    const float fy0f = (float)fy0;
    const int   gy0  = max(fy0, 0);
    const int   gy1  = min(fy0 + 1, 15);

    // ---- build table: 1024 entries, 4 per thread; z = lane-fast (conflict-free) ----
    {
        const int z    = tid & 7;
        const int rest = tid >> 3;         // 0..31
        const int xlq  = rest & 15;        // 4-px group 0..15
        const int sy   = rest >> 4;
        const int half = xlq >> 3;         // 0: xl<32 (fx0=tx-1), 1: xl>=32

        const int gy  = sy ? gy1 : gy0;
        const int gxa = half ? tx : max(tx - 1, 0);
        const int gxb = half ? min(tx + 1, 15) : tx;

        const float4* s0p = (const float4*)&g_repack[(((b * 16 + gy) * 16 + gxa) * 8 + z) * 16];
        const float4* s1p = (const float4*)&g_repack[(((b * 16 + gy) * 16 + gxb) * 8 + z) * 16];
        const float4 s0a = s0p[0], s0b = s0p[1], s0c = s0p[2];
        const float4 s1a = s1p[0], s1b = s1p[1], s1c = s1p[2];
        const float4 da = make_float4(s1a.x - s0a.x, s1a.y - s0a.y, s1a.z - s0a.z, s1a.w - s0a.w);
        const float4 db = make_float4(s1b.x - s0b.x, s1b.y - s0b.y, s1b.z - s0b.z, s1b.w - s0b.w);
        const float4 dc = make_float4(s1c.x - s0c.x, s1c.y - s0c.y, s1c.z - s0c.z, s1c.w - s0c.w);

        const int   xlb = xlq << 2;
        // wx = (xl+0.5)/64 + (half ? -0.5 : 0.5)
        const float wxb = ((float)xlb + 0.5f) * (1.0f / 64.0f) + (half ? -0.5f : 0.5f);

        #pragma unroll
        for (int k = 0; k < 4; k++) {
            const float wx = wxb + (float)k * (1.0f / 64.0f);
            float4* dst = (float4*)&T[sy * SYS + (xlb + k) * XS + z * ZS];
            dst[0] = make_float4(fmaf(wx, da.x, s0a.x), fmaf(wx, da.y, s0a.y),
                                 fmaf(wx, da.z, s0a.z), fmaf(wx, da.w, s0a.w));
            dst[1] = make_float4(fmaf(wx, db.x, s0b.x), fmaf(wx, db.y, s0b.y),
                                 fmaf(wx, db.z, s0b.z), fmaf(wx, db.w, s0b.w));
            dst[2] = make_float4(fmaf(wx, dc.x, s0c.x), fmaf(wx, dc.y, s0c.y),
                                 fmaf(wx, dc.z, s0c.z), fmaf(wx, dc.w, s0c.w));
        }
    }
    __syncthreads();

    // ---- main: thread = (8-px chunk, row). 8-lane phases share the chunk ->
    //      table LDS diverges only in z -> conflict-free / broadcast. ----
    const int lane   = tid & 31;
    const int warp   = tid >> 5;
    const int sub    = lane >> 3;          // 0..3
    const int rphase = lane & 7;           // 0..7
    const int chunk  = ((warp & 1) << 2) + sub;     // 0..7  (8 px each)
    const int row    = ((warp >> 1) << 3) + rphase; // 0..31

    const int x0 = chunk << 3;             // local x base 0..56
    const int y  = r0 + row;

    const float wy  = ((float)y + 0.5f) * (1.0f / 64.0f) - 0.5f - fy0f;
    const float wy0 = 1.0f - wy;

    const size_t gBase  = (size_t)b * 1048576u + ((size_t)y << 10) + (size_t)((tx << 6) + x0);
    const size_t frBase = (size_t)b * 3145728u + ((size_t)y << 10) + (size_t)((tx << 6) + x0);

    #pragma unroll
    for (int q = 0; q < 2; q++) {          // two 4-px quads
        const int qo = q << 2;
        // Streaming loads: bypass L1 line allocation (no cross-use reuse).
        const float4 g4  = __ldcs((const float4*)&guide[gBase + qo]);
        const float4 fc0 = __ldcs((const float4*)&fr[frBase + qo]);
        const float4 fc1 = __ldcs((const float4*)&fr[frBase + qo + 1048576u]);
        const float4 fc2 = __ldcs((const float4*)&fr[frBase + qo + 2097152u]);

        const float ga[4]  = {g4.x, g4.y, g4.z, g4.w};
        const float f0a[4] = {fc0.x, fc0.y, fc0.z, fc0.w};
        const float f1a[4] = {fc1.x, fc1.y, fc1.z, fc1.w};
        const float f2a[4] = {fc2.x, fc2.y, fc2.z, fc2.w};

        float o0[4], o1[4], o2[4];

        #pragma unroll
        for (int p = 0; p < 4; p++) {
            const float gz   = ga[p] * 8.0f - 0.5f;
            const float fz0f = floorf(gz);
            const float wz   = gz - fz0f;
            const int   fz0  = (int)fz0f;
            const int   z0   = max(fz0, 0);
            const int   z1   = min(fz0 + 1, 7);

            const float w00 = wy0 * (1.0f - wz);
            const float w01 = wy0 * wz;
            const float w10 = wy  * (1.0f - wz);
            const float w11 = wy  * wz;

            const int xb = (x0 + qo + p) * XS;
            const float4* t00 = (const float4*)&T[xb + z0 * ZS];
            const float4* t01 = (const float4*)&T[xb + z1 * ZS];
            const float4* t10 = (const float4*)&T[SYS + xb + z0 * ZS];
            const float4* t11 = (const float4*)&T[SYS + xb + z1 * ZS];

            float4 A  = make_float4(0.f, 0.f, 0.f, 0.f);
            float4 Bv = A, Cv = A;

            fma4(A, w00, t00[0]); fma4(Bv, w00, t00[1]); fma4(Cv, w00, t00[2]);
            fma4(A, w01, t01[0]); fma4(Bv, w01, t01[1]); fma4(Cv, w01, t01[2]);
            fma4(A, w10, t10[0]); fma4(Bv, w10, t10[1]); fma4(Cv, w10, t10[2]);
            fma4(A, w11, t11[0]); fma4(Bv, w11, t11[1]); fma4(Cv, w11, t11[2]);

            const float f0p = f0a[p], f1p = f1a[p], f2p = f2a[p];
            o0[p] = fmaf(A.x,  f0p, fmaf(A.y,  f1p, fmaf(A.z,  f2p, A.w)));
            o1[p] = fmaf(Bv.x, f0p, fmaf(Bv.y, f1p, fmaf(Bv.z, f2p, Bv.w)));
            o2[p] = fmaf(Cv.x, f0p, fmaf(Cv.y, f1p, fmaf(Cv.z, f2p, Cv.w)));
        }

        // Streaming stores: avoid L1 write allocation.
        __stcs((float4*)&out[frBase + qo],            make_float4(o0[0], o0[1], o0[2], o0[3]));
        __stcs((float4*)&out[frBase + qo + 1048576u], make_float4(o1[0], o1[1], o1[2], o1[3]));
        __stcs((float4*)&out[frBase + qo + 2097152u], make_float4(o2[0], o2[1], o2[2], o2[3]));
    }
}

extern "C" void kernel_launch(void* const* d_in, const int* in_sizes, int n_in,
                              void* d_out, int out_size) {
    const float* G     = nullptr;
    const float* guide = nullptr;
    const float* fr    = nullptr;
    for (int i = 0; i < n_in; i++) {
        if (in_sizes[i] == 98304)          G     = (const float*)d_in[i];
        else if (in_sizes[i] == 4194304)   guide = (const float*)d_in[i];
        else if (in_sizes[i] == 12582912)  fr    = (const float*)d_in[i];
    }
    if (!G)     G     = (const float*)d_in[0];
    if (!guide) guide = (const float*)d_in[1];
    if (!fr)    fr    = (const float*)d_in[2];

    float* out = (float*)d_out;

    cudaFuncSetAttribute(slice_apply_kernel,
                         cudaFuncAttributeMaxDynamicSharedMemorySize, 49152);

    repack_kernel<<<512, 256>>>(G);

    dim3 grid(16, 32, 4);   // x-tiles(64px), y-tiles(32rows), batch
    slice_apply_kernel<<<grid, 256, 49152>>>(guide, fr, out);
}

// round 8
// speedup vs baseline: 1.0060x; 1.0010x over previous
#include <cuda_runtime.h>

// Repacked grid: [B=4][Hg=16][Wg=16][D=8][16ch(pad)] = 131072 floats
__device__ float g_repack[4 * 16 * 16 * 8 * 16];

__global__ void repack_kernel(const float* __restrict__ G) {
    int i = blockIdx.x * blockDim.x + threadIdx.x;  // 131072 threads
    int c = i & 15;
    int t = i >> 4;
    int z = t & 7;  t >>= 3;
    int x = t & 15; t >>= 4;
    int y = t & 15;
    int b = t >> 4;
    float v = 0.0f;
    if (c < 12) {
        v = G[((b * 12 + c) * 8 + z) * 256 + y * 16 + x];
    }
    g_repack[i] = v;
}

// Shared x-interp table: T[sy][xl][z][12]
//   entry = 12 floats (48B = 3 16B-units; 3*z mod 8 is a permutation ->
//   z-divergent LDS.128 within an 8-lane phase is conflict-free)
//   xl stride 96 floats, sy stride 6144 floats. Total 49152B.
#define ZS 12
#define XS 96
#define SYS 6144

__device__ __forceinline__ void fma4(float4& acc, float w, const float4 v) {
    acc.x = fmaf(w, v.x, acc.x);
    acc.y = fmaf(w, v.y, acc.y);
    acc.z = fmaf(w, v.z, acc.z);
    acc.w = fmaf(w, v.w, acc.w);
}

__global__ __launch_bounds__(256, 4) void slice_apply_kernel(
    const float* __restrict__ guide,
    const float* __restrict__ fr,
    float* __restrict__ out)
{
    extern __shared__ float T[];

    const int b   = blockIdx.z;
    const int tx  = blockIdx.x;        // x grid-cell (tile 64 px wide)
    const int by  = blockIdx.y;        // 32-row tile index
    const int r0  = by << 5;
    const int tid = threadIdx.x;

    // 32-row aligned tiles never cross an fy boundary (boundaries at y=32+64k)
    const int   fy0  = (by - 1) >> 1;
    const float fy0f = (float)fy0;
    const int   gy0  = max(fy0, 0);
    const int   gy1  = min(fy0 + 1, 15);

    // ---- build table: 1024 entries, 4 per thread; z = lane-fast (conflict-free) ----
    {
        const int z    = tid & 7;
        const int rest = tid >> 3;         // 0..31
        const int xlq  = rest & 15;        // 4-px group 0..15
        const int sy   = rest >> 4;
        const int half = xlq >> 3;         // 0: xl<32 (fx0=tx-1), 1: xl>=32

        const int gy  = sy ? gy1 : gy0;
        const int gxa = half ? tx : max(tx - 1, 0);
        const int gxb = half ? min(tx + 1, 15) : tx;

        const float4* s0p = (const float4*)&g_repack[(((b * 16 + gy) * 16 + gxa) * 8 + z) * 16];
        const float4* s1p = (const float4*)&g_repack[(((b * 16 + gy) * 16 + gxb) * 8 + z) * 16];
        const float4 s0a = s0p[0], s0b = s0p[1], s0c = s0p[2];
        const float4 s1a = s1p[0], s1b = s1p[1], s1c = s1p[2];
        const float4 da = make_float4(s1a.x - s0a.x, s1a.y - s0a.y, s1a.z - s0a.z, s1a.w - s0a.w);
        const float4 db = make_float4(s1b.x - s0b.x, s1b.y - s0b.y, s1b.z - s0b.z, s1b.w - s0b.w);
        const float4 dc = make_float4(s1c.x - s0c.x, s1c.y - s0c.y, s1c.z - s0c.z, s1c.w - s0c.w);

        const int   xlb = xlq << 2;
        // wx = (xl+0.5)/64 + (half ? -0.5 : 0.5)
        const float wxb = ((float)xlb + 0.5f) * (1.0f / 64.0f) + (half ? -0.5f : 0.5f);

        #pragma unroll
        for (int k = 0; k < 4; k++) {
            const float wx = wxb + (float)k * (1.0f / 64.0f);
            float4* dst = (float4*)&T[sy * SYS + (xlb + k) * XS + z * ZS];
            dst[0] = make_float4(fmaf(wx, da.x, s0a.x), fmaf(wx, da.y, s0a.y),
                                 fmaf(wx, da.z, s0a.z), fmaf(wx, da.w, s0a.w));
            dst[1] = make_float4(fmaf(wx, db.x, s0b.x), fmaf(wx, db.y, s0b.y),
                                 fmaf(wx, db.z, s0b.z), fmaf(wx, db.w, s0b.w));
            dst[2] = make_float4(fmaf(wx, dc.x, s0c.x), fmaf(wx, dc.y, s0c.y),
                                 fmaf(wx, dc.z, s0c.z), fmaf(wx, dc.w, s0c.w));
        }
    }
    __syncthreads();

    // ---- main: thread = (8-px chunk, row). 8-lane phases share the chunk ->
    //      table LDS diverges only in z -> conflict-free / broadcast. ----
    const int lane   = tid & 31;
    const int warp   = tid >> 5;
    const int sub    = lane >> 3;          // 0..3
    const int rphase = lane & 7;           // 0..7
    const int chunk  = ((warp & 1) << 2) + sub;     // 0..7  (8 px each)
    const int row    = ((warp >> 1) << 3) + rphase; // 0..31

    const int x0 = chunk << 3;             // local x base 0..56
    const int y  = r0 + row;

    const float wy  = ((float)y + 0.5f) * (1.0f / 64.0f) - 0.5f - fy0f;
    const float wy0 = 1.0f - wy;

    const size_t gBase  = (size_t)b * 1048576u + ((size_t)y << 10) + (size_t)((tx << 6) + x0);
    const size_t frBase = (size_t)b * 3145728u + ((size_t)y << 10) + (size_t)((tx << 6) + x0);

    #pragma unroll
    for (int q = 0; q < 2; q++) {          // two 4-px quads
        const int qo = q << 2;
        // Streaming loads: bypass L1 line allocation (no cross-use reuse).
        const float4 g4  = __ldcs((const float4*)&guide[gBase + qo]);
        const float4 fc0 = __ldcs((const float4*)&fr[frBase + qo]);
        const float4 fc1 = __ldcs((const float4*)&fr[frBase + qo + 1048576u]);
        const float4 fc2 = __ldcs((const float4*)&fr[frBase + qo + 2097152u]);

        const float ga[4]  = {g4.x, g4.y, g4.z, g4.w};
        const float f0a[4] = {fc0.x, fc0.y, fc0.z, fc0.w};
        const float f1a[4] = {fc1.x, fc1.y, fc1.z, fc1.w};
        const float f2a[4] = {fc2.x, fc2.y, fc2.z, fc2.w};

        float o0[4], o1[4], o2[4];

        #pragma unroll
        for (int p = 0; p < 4; p++) {
            const float gz   = ga[p] * 8.0f - 0.5f;
            const float fz0f = floorf(gz);
            const float wz   = gz - fz0f;
            const int   fz0  = (int)fz0f;
            const int   z0   = max(fz0, 0);
            const int   z1   = min(fz0 + 1, 7);

            const float w00 = wy0 * (1.0f - wz);
            const float w01 = wy0 * wz;
            const float w10 = wy  * (1.0f - wz);
            const float w11 = wy  * wz;

            const int xb = (x0 + qo + p) * XS;
            const float4* t00 = (const float4*)&T[xb + z0 * ZS];
            const float4* t01 = (const float4*)&T[xb + z1 * ZS];
            const float4* t10 = (const float4*)&T[SYS + xb + z0 * ZS];
            const float4* t11 = (const float4*)&T[SYS + xb + z1 * ZS];

            float4 A  = make_float4(0.f, 0.f, 0.f, 0.f);
            float4 Bv = A, Cv = A;

            fma4(A, w00, t00[0]); fma4(Bv, w00, t00[1]); fma4(Cv, w00, t00[2]);
            fma4(A, w01, t01[0]); fma4(Bv, w01, t01[1]); fma4(Cv, w01, t01[2]);
            fma4(A, w10, t10[0]); fma4(Bv, w10, t10[1]); fma4(Cv, w10, t10[2]);
            fma4(A, w11, t11[0]); fma4(Bv, w11, t11[1]); fma4(Cv, w11, t11[2]);

            const float f0p = f0a[p], f1p = f1a[p], f2p = f2a[p];
            o0[p] = fmaf(A.x,  f0p, fmaf(A.y,  f1p, fmaf(A.z,  f2p, A.w)));
            o1[p] = fmaf(Bv.x, f0p, fmaf(Bv.y, f1p, fmaf(Bv.z, f2p, Bv.w)));
            o2[p] = fmaf(Cv.x, f0p, fmaf(Cv.y, f1p, fmaf(Cv.z, f2p, Cv.w)));
        }

        // Streaming stores: avoid L1 write allocation.
        __stcs((float4*)&out[frBase + qo],            make_float4(o0[0], o0[1], o0[2], o0[3]));
        __stcs((float4*)&out[frBase + qo + 1048576u], make_float4(o1[0], o1[1], o1[2], o1[3]));
        __stcs((float4*)&out[frBase + qo + 2097152u], make_float4(o2[0], o2[1], o2[2], o2[3]));
    }
}

extern "C" void kernel_launch(void* const* d_in, const int* in_sizes, int n_in,
                              void* d_out, int out_size) {
    const float* G     = nullptr;
    const float* guide = nullptr;
    const float* fr    = nullptr;
    for (int i = 0; i < n_in; i++) {
        if (in_sizes[i] == 98304)          G     = (const float*)d_in[i];
        else if (in_sizes[i] == 4194304)   guide = (const float*)d_in[i];
        else if (in_sizes[i] == 12582912)  fr    = (const float*)d_in[i];
    }
    if (!G)     G     = (const float*)d_in[0];
    if (!guide) guide = (const float*)d_in[1];
    if (!fr)    fr    = (const float*)d_in[2];

    float* out = (float*)d_out;

    cudaFuncSetAttribute(slice_apply_kernel,
                         cudaFuncAttributeMaxDynamicSharedMemorySize, 49152);

    repack_kernel<<<512, 256>>>(G);

    dim3 grid(16, 32, 4);   // x-tiles(64px), y-tiles(32rows), batch
    slice_apply_kernel<<<grid, 256, 49152>>>(guide, fr, out);
}

// round 9
// speedup vs baseline: 1.0325x; 1.0263x over previous
#include <cuda_runtime.h>

// Repacked grid: [B=4][Hg=16][Wg=16][D=8][16ch(pad)] = 131072 floats
__device__ float g_repack[4 * 16 * 16 * 8 * 16];

__global__ void repack_kernel(const float* __restrict__ G) {
    int i = blockIdx.x * blockDim.x + threadIdx.x;  // 131072 threads
    int c = i & 15;
    int t = i >> 4;
    int z = t & 7;  t >>= 3;
    int x = t & 15; t >>= 4;
    int y = t & 15;
    int b = t >> 4;
    float v = 0.0f;
    if (c < 12) {
        v = G[((b * 12 + c) * 8 + z) * 256 + y * 16 + x];
    }
    g_repack[i] = v;
}

// Shared x-interp table: T[sy][xl][z][12]
//   entry = 12 floats (48B = 3 16B-units; 3*z mod 8 is a permutation ->
//   z-divergent LDS.128 within an 8-lane phase is conflict-free)
//   xl stride 96 floats, sy stride 6144 floats. Total 49152B.
#define ZS 12
#define XS 96
#define SYS 6144

__device__ __forceinline__ void fma4(float4& acc, float w, const float4 v) {
    acc.x = fmaf(w, v.x, acc.x);
    acc.y = fmaf(w, v.y, acc.y);
    acc.z = fmaf(w, v.z, acc.z);
    acc.w = fmaf(w, v.w, acc.w);
}

__global__ __launch_bounds__(256, 4) void slice_apply_kernel(
    const float* __restrict__ guide,
    const float* __restrict__ fr,
    float* __restrict__ out)
{
    extern __shared__ float T[];

    const int b   = blockIdx.z;
    const int tx  = blockIdx.x;        // x grid-cell (tile 64 px wide)
    const int by  = blockIdx.y;        // 32-row tile index
    const int r0  = by << 5;
    const int tid = threadIdx.x;

    // 32-row aligned tiles never cross an fy boundary (boundaries at y=32+64k)
    const int   fy0  = (by - 1) >> 1;
    const float fy0f = (float)fy0;
    const int   gy0  = max(fy0, 0);
    const int   gy1  = min(fy0 + 1, 15);

    // ---- build table: 1024 entries, 4 per thread; z = lane-fast (conflict-free) ----
    {
        const int z    = tid & 7;
        const int rest = tid >> 3;         // 0..31
        const int xlq  = rest & 15;        // 4-px group 0..15
        const int sy   = rest >> 4;
        const int half = xlq >> 3;         // 0: xl<32 (fx0=tx-1), 1: xl>=32

        const int gy  = sy ? gy1 : gy0;
        const int gxa = half ? tx : max(tx - 1, 0);
        const int gxb = half ? min(tx + 1, 15) : tx;

        const float4* s0p = (const float4*)&g_repack[(((b * 16 + gy) * 16 + gxa) * 8 + z) * 16];
        const float4* s1p = (const float4*)&g_repack[(((b * 16 + gy) * 16 + gxb) * 8 + z) * 16];
        const float4 s0a = s0p[0], s0b = s0p[1], s0c = s0p[2];
        const float4 s1a = s1p[0], s1b = s1p[1], s1c = s1p[2];
        const float4 da = make_float4(s1a.x - s0a.x, s1a.y - s0a.y, s1a.z - s0a.z, s1a.w - s0a.w);
        const float4 db = make_float4(s1b.x - s0b.x, s1b.y - s0b.y, s1b.z - s0b.z, s1b.w - s0b.w);
        const float4 dc = make_float4(s1c.x - s0c.x, s1c.y - s0c.y, s1c.z - s0c.z, s1c.w - s0c.w);

        const int   xlb = xlq << 2;
        // wx = (xl+0.5)/64 + (half ? -0.5 : 0.5)
        const float wxb = ((float)xlb + 0.5f) * (1.0f / 64.0f) + (half ? -0.5f : 0.5f);

        #pragma unroll
        for (int k = 0; k < 4; k++) {
            const float wx = wxb + (float)k * (1.0f / 64.0f);
            float4* dst = (float4*)&T[sy * SYS + (xlb + k) * XS + z * ZS];
            dst[0] = make_float4(fmaf(wx, da.x, s0a.x), fmaf(wx, da.y, s0a.y),
                                 fmaf(wx, da.z, s0a.z), fmaf(wx, da.w, s0a.w));
            dst[1] = make_float4(fmaf(wx, db.x, s0b.x), fmaf(wx, db.y, s0b.y),
                                 fmaf(wx, db.z, s0b.z), fmaf(wx, db.w, s0b.w));
            dst[2] = make_float4(fmaf(wx, dc.x, s0c.x), fmaf(wx, dc.y, s0c.y),
                                 fmaf(wx, dc.z, s0c.z), fmaf(wx, dc.w, s0c.w));
        }
    }
    __syncthreads();

    // ---- main: thread = (8-px chunk, row). 8-lane phases share the chunk ->
    //      table LDS diverges only in z -> conflict-free / broadcast. ----
    const int lane   = tid & 31;
    const int warp   = tid >> 5;
    const int sub    = lane >> 3;          // 0..3
    const int rphase = lane & 7;           // 0..7
    const int chunk  = ((warp & 1) << 2) + sub;     // 0..7  (8 px each)
    const int row    = ((warp >> 1) << 3) + rphase; // 0..31

    const int x0 = chunk << 3;             // local x base 0..56
    const int y  = r0 + row;

    const float wy  = ((float)y + 0.5f) * (1.0f / 64.0f) - 0.5f - fy0f;
    const float wy0 = 1.0f - wy;

    const size_t gBase  = (size_t)b * 1048576u + ((size_t)y << 10) + (size_t)((tx << 6) + x0);
    const size_t frBase = (size_t)b * 3145728u + ((size_t)y << 10) + (size_t)((tx << 6) + x0);

    #pragma unroll
    for (int q = 0; q < 2; q++) {          // two 4-px quads
        const int qo = q << 2;
        // Streaming loads: bypass L1 line allocation (no cross-use reuse).
        const float4 g4  = __ldcs((const float4*)&guide[gBase + qo]);
        const float4 fc0 = __ldcs((const float4*)&fr[frBase + qo]);
        const float4 fc1 = __ldcs((const float4*)&fr[frBase + qo + 1048576u]);
        const float4 fc2 = __ldcs((const float4*)&fr[frBase + qo + 2097152u]);

        const float ga[4]  = {g4.x, g4.y, g4.z, g4.w};
        const float f0a[4] = {fc0.x, fc0.y, fc0.z, fc0.w};
        const float f1a[4] = {fc1.x, fc1.y, fc1.z, fc1.w};
        const float f2a[4] = {fc2.x, fc2.y, fc2.z, fc2.w};

        float o0[4], o1[4], o2[4];

        #pragma unroll
        for (int p = 0; p < 4; p++) {
            const float gz   = ga[p] * 8.0f - 0.5f;
            const float fz0f = floorf(gz);
            const float wz   = gz - fz0f;
            const int   fz0  = (int)fz0f;
            const int   z0   = max(fz0, 0);
            const int   z1   = min(fz0 + 1, 7);

            const float w00 = wy0 * (1.0f - wz);
            const float w01 = wy0 * wz;
            const float w10 = wy  * (1.0f - wz);
            const float w11 = wy  * wz;

            const int xb = (x0 + qo + p) * XS;
            const float4* t00 = (const float4*)&T[xb + z0 * ZS];
            const float4* t01 = (const float4*)&T[xb + z1 * ZS];
            const float4* t10 = (const float4*)&T[SYS + xb + z0 * ZS];
            const float4* t11 = (const float4*)&T[SYS + xb + z1 * ZS];

            float4 A  = make_float4(0.f, 0.f, 0.f, 0.f);
            float4 Bv = A, Cv = A;

            fma4(A, w00, t00[0]); fma4(Bv, w00, t00[1]); fma4(Cv, w00, t00[2]);
            fma4(A, w01, t01[0]); fma4(Bv, w01, t01[1]); fma4(Cv, w01, t01[2]);
            fma4(A, w10, t10[0]); fma4(Bv, w10, t10[1]); fma4(Cv, w10, t10[2]);
            fma4(A, w11, t11[0]); fma4(Bv, w11, t11[1]); fma4(Cv, w11, t11[2]);

            const float f0p = f0a[p], f1p = f1a[p], f2p = f2a[p];
            o0[p] = fmaf(A.x,  f0p, fmaf(A.y,  f1p, fmaf(A.z,  f2p, A.w)));
            o1[p] = fmaf(Bv.x, f0p, fmaf(Bv.y, f1p, fmaf(Bv.z, f2p, Bv.w)));
            o2[p] = fmaf(Cv.x, f0p, fmaf(Cv.y, f1p, fmaf(Cv.z, f2p, Cv.w)));
        }

        // Streaming stores: avoid L1 write allocation.
        __stcs((float4*)&out[frBase + qo],            make_float4(o0[0], o0[1], o0[2], o0[3]));
        __stcs((float4*)&out[frBase + qo + 1048576u], make_float4(o1[0], o1[1], o1[2], o1[3]));
        __stcs((float4*)&out[frBase + qo + 2097152u], make_float4(o2[0], o2[1], o2[2], o2[3]));
    }
}

extern "C" void kernel_launch(void* const* d_in, const int* in_sizes, int n_in,
                              void* d_out, int out_size) {
    const float* G     = nullptr;
    const float* guide = nullptr;
    const float* fr    = nullptr;
    for (int i = 0; i < n_in; i++) {
        if (in_sizes[i] == 98304)          G     = (const float*)d_in[i];
        else if (in_sizes[i] == 4194304)   guide = (const float*)d_in[i];
        else if (in_sizes[i] == 12582912)  fr    = (const float*)d_in[i];
    }
    if (!G)     G     = (const float*)d_in[0];
    if (!guide) guide = (const float*)d_in[1];
    if (!fr)    fr    = (const float*)d_in[2];

    float* out = (float*)d_out;

    cudaFuncSetAttribute(slice_apply_kernel,
                         cudaFuncAttributeMaxDynamicSharedMemorySize, 49152);

    repack_kernel<<<512, 256>>>(G);

    dim3 grid(16, 32, 4);   // x-tiles(64px), y-tiles(32rows), batch
    slice_apply_kernel<<<grid, 256, 49152>>>(guide, fr, out);
}

// round 10
// speedup vs baseline: 1.2315x; 1.1927x over previous
#include <cuda_runtime.h>
#include <cuda_fp16.h>

// Repacked grid: [B=4][Hg=16][Wg=16][D=8][16ch(pad)] = 131072 floats
__device__ float g_repack[4 * 16 * 16 * 8 * 16];

__global__ void repack_kernel(const float* __restrict__ G) {
    int i = blockIdx.x * blockDim.x + threadIdx.x;  // 131072 threads
    int c = i & 15;
    int t = i >> 4;
    int z = t & 7;  t >>= 3;
    int x = t & 15; t >>= 4;
    int y = t & 15;
    int b = t >> 4;
    float v = 0.0f;
    if (c < 12) {
        v = G[((b * 12 + c) * 8 + z) * 256 + y * 16 + x];
    }
    g_repack[i] = v;
}

union U4 {
    uint4 u;
    __half2 h[4];
};

__global__ __launch_bounds__(256, 4) void slice_apply_kernel(
    const float* __restrict__ guide,
    const float* __restrict__ fr,
    float* __restrict__ out)
{
    // Ta[sy][xl][z]: ch0-7 as 8 halves (16B). addr16 = (sy*64+xl)*8+z -> mod 8 = z.
    // Tb[xl][z]: {sy0 ch8-11, sy1 ch8-11} as 8 halves (16B). addr16 mod 8 = z.
    __shared__ uint4 TaS[2 * 64 * 8];   // 16KB
    __shared__ uint4 TbS[64 * 8];       // 8KB

    const int b   = blockIdx.z;
    const int tx  = blockIdx.x;        // x grid-cell (tile 64 px wide)
    const int by  = blockIdx.y;        // 32-row tile index
    const int r0  = by << 5;
    const int tid = threadIdx.x;

    // 32-row aligned tiles never cross an fy boundary (boundaries at y=32+64k)
    const int   fy0  = (by - 1) >> 1;
    const float fy0f = (float)fy0;
    const int   gy0  = max(fy0, 0);
    const int   gy1  = min(fy0 + 1, 15);

    // ---- build fp16 tables: 1024 (sy,xl,z) entries, 4 per thread; z lane-fast ----
    {
        const int z    = tid & 7;
        const int rest = tid >> 3;         // 0..31
        const int xlq  = rest & 15;        // 4-px group 0..15
        const int sy   = rest >> 4;
        const int half = xlq >> 3;         // 0: xl<32 (fx0=tx-1), 1: xl>=32

        const int gy  = sy ? gy1 : gy0;
        const int gxa = half ? tx : max(tx - 1, 0);
        const int gxb = half ? min(tx + 1, 15) : tx;

        const float4* s0p = (const float4*)&g_repack[(((b * 16 + gy) * 16 + gxa) * 8 + z) * 16];
        const float4* s1p = (const float4*)&g_repack[(((b * 16 + gy) * 16 + gxb) * 8 + z) * 16];
        const float4 s0a = s0p[0], s0b = s0p[1], s0c = s0p[2];
        const float4 s1a = s1p[0], s1b = s1p[1], s1c = s1p[2];
        const float4 da = make_float4(s1a.x - s0a.x, s1a.y - s0a.y, s1a.z - s0a.z, s1a.w - s0a.w);
        const float4 db = make_float4(s1b.x - s0b.x, s1b.y - s0b.y, s1b.z - s0b.z, s1b.w - s0b.w);
        const float4 dc = make_float4(s1c.x - s0c.x, s1c.y - s0c.y, s1c.z - s0c.z, s1c.w - s0c.w);

        const int   xlb = xlq << 2;
        // wx = (xl+0.5)/64 + (half ? -0.5 : 0.5)
        const float wxb = ((float)xlb + 0.5f) * (1.0f / 64.0f) + (half ? -0.5f : 0.5f);

        #pragma unroll
        for (int k = 0; k < 4; k++) {
            const float wx = wxb + (float)k * (1.0f / 64.0f);
            const float c0 = fmaf(wx, da.x, s0a.x), c1 = fmaf(wx, da.y, s0a.y);
            const float c2 = fmaf(wx, da.z, s0a.z), c3 = fmaf(wx, da.w, s0a.w);
            const float c4 = fmaf(wx, db.x, s0b.x), c5 = fmaf(wx, db.y, s0b.y);
            const float c6 = fmaf(wx, db.z, s0b.z), c7 = fmaf(wx, db.w, s0b.w);
            const float c8 = fmaf(wx, dc.x, s0c.x), c9 = fmaf(wx, dc.y, s0c.y);
            const float cA = fmaf(wx, dc.z, s0c.z), cB = fmaf(wx, dc.w, s0c.w);

            U4 ta;
            ta.h[0] = __floats2half2_rn(c0, c1);
            ta.h[1] = __floats2half2_rn(c2, c3);
            ta.h[2] = __floats2half2_rn(c4, c5);
            ta.h[3] = __floats2half2_rn(c6, c7);
            TaS[(sy * 64 + xlb + k) * 8 + z] = ta.u;

            __half2 tb0 = __floats2half2_rn(c8, c9);
            __half2 tb1 = __floats2half2_rn(cA, cB);
            __half2* tbp = (__half2*)&TbS[(xlb + k) * 8 + z];
            tbp[sy * 2 + 0] = tb0;
            tbp[sy * 2 + 1] = tb1;
        }
    }
    __syncthreads();

    // ---- main: thread = (8-px chunk, row). 8-lane phases share the chunk ->
    //      table LDS diverges only in z -> conflict-free / broadcast. ----
    const int lane   = tid & 31;
    const int warp   = tid >> 5;
    const int sub    = lane >> 3;          // 0..3
    const int rphase = lane & 7;           // 0..7
    const int chunk  = ((warp & 1) << 2) + sub;     // 0..7  (8 px each)
    const int row    = ((warp >> 1) << 3) + rphase; // 0..31

    const int x0 = chunk << 3;             // local x base 0..56
    const int y  = r0 + row;

    const float wy  = ((float)y + 0.5f) * (1.0f / 64.0f) - 0.5f - fy0f;
    const float wy0 = 1.0f - wy;

    const size_t gBase  = (size_t)b * 1048576u + ((size_t)y << 10) + (size_t)((tx << 6) + x0);
    const size_t frBase = (size_t)b * 3145728u + ((size_t)y << 10) + (size_t)((tx << 6) + x0);

    #pragma unroll
    for (int q = 0; q < 2; q++) {          // two 4-px quads
        const int qo = q << 2;
        const float4 g4  = __ldcs((const float4*)&guide[gBase + qo]);
        const float4 fc0 = __ldcs((const float4*)&fr[frBase + qo]);
        const float4 fc1 = __ldcs((const float4*)&fr[frBase + qo + 1048576u]);
        const float4 fc2 = __ldcs((const float4*)&fr[frBase + qo + 2097152u]);

        const float ga[4]  = {g4.x, g4.y, g4.z, g4.w};
        const float f0a[4] = {fc0.x, fc0.y, fc0.z, fc0.w};
        const float f1a[4] = {fc1.x, fc1.y, fc1.z, fc1.w};
        const float f2a[4] = {fc2.x, fc2.y, fc2.z, fc2.w};

        float o0[4], o1[4], o2[4];

        #pragma unroll
        for (int p = 0; p < 4; p++) {
            const float gz   = ga[p] * 8.0f - 0.5f;
            const float fz0f = floorf(gz);
            const float wz   = gz - fz0f;
            const int   fz0  = (int)fz0f;
            const int   z0   = max(fz0, 0);
            const int   z1   = min(fz0 + 1, 7);

            const __half2 hw0 = __float2half2_rn(1.0f - wz);
            const __half2 hw1 = __float2half2_rn(wz);

            const int eb = (x0 + qo + p) * 8;     // entry base for this xl

            U4 a00, a01, a10, a11, b0, b1;
            a00.u = TaS[eb + z0];
            a01.u = TaS[eb + z1];
            a10.u = TaS[512 + eb + z0];
            a11.u = TaS[512 + eb + z1];
            b0.u  = TbS[eb + z0];
            b1.u  = TbS[eb + z1];

            // z-combine in fp16 (weights identical for both sy)
            __half2 ca0[4], ca1[4], cb[4];
            #pragma unroll
            for (int i = 0; i < 4; i++) {
                ca0[i] = __hfma2(hw0, a00.h[i], __hmul2(hw1, a01.h[i]));
                ca1[i] = __hfma2(hw0, a10.h[i], __hmul2(hw1, a11.h[i]));
                cb[i]  = __hfma2(hw0, b0.h[i],  __hmul2(hw1, b1.h[i]));
            }

            // convert + y-lerp in fp32
            float c[12];
            #pragma unroll
            for (int i = 0; i < 4; i++) {
                const float2 u0 = __half22float2(ca0[i]);
                const float2 u1 = __half22float2(ca1[i]);
                c[2 * i]     = fmaf(wy, u1.x - u0.x, u0.x);
                c[2 * i + 1] = fmaf(wy, u1.y - u0.y, u0.y);
            }
            {
                const float2 s0l = __half22float2(cb[0]);   // sy0 ch8,9
                const float2 s0h = __half22float2(cb[1]);   // sy0 ch10,11
                const float2 s1l = __half22float2(cb[2]);   // sy1 ch8,9
                const float2 s1h = __half22float2(cb[3]);   // sy1 ch10,11
                c[8]  = fmaf(wy, s1l.x - s0l.x, s0l.x);
                c[9]  = fmaf(wy, s1l.y - s0l.y, s0l.y);
                c[10] = fmaf(wy, s1h.x - s0h.x, s0h.x);
                c[11] = fmaf(wy, s1h.y - s0h.y, s0h.y);
            }

            const float f0p = f0a[p], f1p = f1a[p], f2p = f2a[p];
            o0[p] = fmaf(c[0], f0p, fmaf(c[1],  f1p, fmaf(c[2],  f2p, c[3])));
            o1[p] = fmaf(c[4], f0p, fmaf(c[5],  f1p, fmaf(c[6],  f2p, c[7])));
            o2[p] = fmaf(c[8], f0p, fmaf(c[9],  f1p, fmaf(c[10], f2p, c[11])));
        }

        __stcs((float4*)&out[frBase + qo],            make_float4(o0[0], o0[1], o0[2], o0[3]));
        __stcs((float4*)&out[frBase + qo + 1048576u], make_float4(o1[0], o1[1], o1[2], o1[3]));
        __stcs((float4*)&out[frBase + qo + 2097152u], make_float4(o2[0], o2[1], o2[2], o2[3]));
    }
}

extern "C" void kernel_launch(void* const* d_in, const int* in_sizes, int n_in,
                              void* d_out, int out_size) {
    const float* G     = nullptr;
    const float* guide = nullptr;
    const float* fr    = nullptr;
    for (int i = 0; i < n_in; i++) {
        if (in_sizes[i] == 98304)          G     = (const float*)d_in[i];
        else if (in_sizes[i] == 4194304)   guide = (const float*)d_in[i];
        else if (in_sizes[i] == 12582912)  fr    = (const float*)d_in[i];
    }
    if (!G)     G     = (const float*)d_in[0];
    if (!guide) guide = (const float*)d_in[1];
    if (!fr)    fr    = (const float*)d_in[2];

    float* out = (float*)d_out;

    repack_kernel<<<512, 256>>>(G);

    dim3 grid(16, 32, 4);   // x-tiles(64px), y-tiles(32rows), batch
    slice_apply_kernel<<<grid, 256>>>(guide, fr, out);
}